// round 10
// baseline (speedup 1.0000x reference)
#include <cuda_runtime.h>
#include <math.h>

#define LSEQ 256
#define EDIM 768
#define HDIM 384
#define NDOM 9
#define BMAX 2048
#define PT 8

// device scratch (no allocation allowed)
__device__ float g_feature[(size_t)BMAX * EDIM];   // [B, 2H]: [shared | specific]
__device__ float g_h1[(size_t)BMAX * 64];
__device__ float g_hdom[(size_t)BMAX * HDIM];
__device__ int   g_counts[16];
__device__ int   g_idx[NDOM * BMAX];
__device__ int   g_flag[BMAX];                     // per-sample "pooled ready"

// ---------------------------------------------------------------------------
// zero flags + counts (must precede scatter/fused kernel; stream-ordered)
// ---------------------------------------------------------------------------
__global__ void zero_kernel(int B) {
    int i = blockIdx.x * blockDim.x + threadIdx.x;
    if (i < B) g_flag[i] = 0;
    if (blockIdx.x == 0 && threadIdx.x < 16) g_counts[threadIdx.x] = 0;
}

__global__ void scatter_kernel(const int* __restrict__ category, int B) {
    int i = blockIdx.x * blockDim.x + threadIdx.x;
    if (i < B) {
        int c = category[i];
        int p = atomicAdd(&g_counts[c], 1);
        g_idx[c * BMAX + p] = i;
    }
}

// ---------------------------------------------------------------------------
// tf32 helpers (3xTF32 compensated; numerics proven: rel_err ~6e-6)
// ---------------------------------------------------------------------------
__device__ __forceinline__ float tf32_trunc(float v) {
    return __uint_as_float(__float_as_uint(v) & 0xFFFFE000u);
}

__device__ __forceinline__ void mma_tf32(float* c,
    float a0, float a1, float a2, float a3, float b0, float b1)
{
    asm volatile(
        "mma.sync.aligned.m16n8k8.row.col.f32.tf32.tf32.f32 "
        "{%0,%1,%2,%3}, {%4,%5,%6,%7}, {%8,%9}, {%0,%1,%2,%3};\n"
        : "+f"(c[0]), "+f"(c[1]), "+f"(c[2]), "+f"(c[3])
        : "r"(__float_as_uint(a0)), "r"(__float_as_uint(a1)),
          "r"(__float_as_uint(a2)), "r"(__float_as_uint(a3)),
          "r"(__float_as_uint(b0)), "r"(__float_as_uint(b1)));
}

// ---------------------------------------------------------------------------
// FUSED pool + expert kernel.
// blocks [0,B): masked-attention pooling for sample bx (192 active threads),
//   sets g_flag[bx] when its pooled row is globally visible.
// blocks [B, B + 10*6*mtiles): 3xTF32 expert/shared GEMM tile; spins on the
//   flags of the <=64 samples its A-tile needs, then runs the R9-proven body.
// In-order CTA dispatch => all pool blocks dispatch before any expert block
// => no deadlock; expert overlaps the pool tail.
// ---------------------------------------------------------------------------
__global__ void __launch_bounds__(256) fused_pool_expert_kernel(
    const float* __restrict__ bert, const int* __restrict__ masks,
    const float* __restrict__ att_w, const float* __restrict__ att_b,
    float* __restrict__ pooled,
    const float* __restrict__ Wsh, const float* __restrict__ bsh,
    const float* __restrict__ Wsp, const float* __restrict__ bsp,
    int B, int mtiles)
{
    __shared__ union {
        struct { float As[2][16][68]; float Bs[2][16][68]; } g;
        struct { float wr[2][PT][8]; int msk[LSEQ]; } p;
    } sm;

    const int t = threadIdx.x;

    if ((int)blockIdx.x < B) {
        // ================= POOL ROLE (R9-proven math; 192 active) ==========
        const int b = blockIdx.x;
        const bool act = (t < 192);
        const int lane = t & 31, wid = t >> 5;
        const float4* base = reinterpret_cast<const float4*>(bert + (size_t)b * LSEQ * EDIM);
        float4 w = make_float4(0.f, 0.f, 0.f, 0.f);
        if (act) w = reinterpret_cast<const float4*>(att_w)[t];
        const float bb = att_b[0];

        for (int i = t; i < LSEQ; i += 256) sm.p.msk[i] = masks[b * LSEQ + i];

        float4 acc = make_float4(0.f, 0.f, 0.f, 0.f);
        float m = -3e38f, d = 0.f;

        float4 x[PT], xn[PT];
        if (act) {
            #pragma unroll
            for (int j = 0; j < PT; ++j) x[j] = base[j * 192 + t];
        }
        __syncthreads();  // msk ready

        const int NC = LSEQ / PT;
        for (int c = 0; c < NC; ++c) {
            const int cb = c & 1;
            if (act) {
                float p[PT];
                #pragma unroll
                for (int j = 0; j < PT; ++j)
                    p[j] = x[j].x * w.x + x[j].y * w.y + x[j].z * w.z + x[j].w * w.w;

                if (c + 1 < NC) {
                    #pragma unroll
                    for (int j = 0; j < PT; ++j)
                        xn[j] = base[((c + 1) * PT + j) * 192 + t];
                }

                #pragma unroll
                for (int j = 0; j < PT; ++j) {
                    #pragma unroll
                    for (int o = 16; o; o >>= 1)
                        p[j] += __shfl_xor_sync(0xffffffffu, p[j], o);
                }
                if (lane == 0) {
                    #pragma unroll
                    for (int j = 0; j < PT; ++j) sm.p.wr[cb][j][wid] = p[j];
                }
            }
            __syncthreads();

            if (act) {
                float s[PT], Mc = -3e38f;
                #pragma unroll
                for (int j = 0; j < PT; ++j) {
                    s[j] = sm.p.wr[cb][j][0] + sm.p.wr[cb][j][1] + sm.p.wr[cb][j][2]
                         + sm.p.wr[cb][j][3] + sm.p.wr[cb][j][4] + sm.p.wr[cb][j][5] + bb;
                    if (sm.p.msk[c * PT + j] == 0) s[j] = -1e9f;
                    Mc = fmaxf(Mc, s[j]);
                }
                float pe[PT], dc = 0.f;
                #pragma unroll
                for (int j = 0; j < PT; ++j) { pe[j] = __expf(s[j] - Mc); dc += pe[j]; }
                float4 ca = make_float4(0.f, 0.f, 0.f, 0.f);
                #pragma unroll
                for (int j = 0; j < PT; ++j) {
                    ca.x += pe[j] * x[j].x; ca.y += pe[j] * x[j].y;
                    ca.z += pe[j] * x[j].z; ca.w += pe[j] * x[j].w;
                }
                const float nm = fmaxf(m, Mc);
                const float fo = __expf(m - nm), fn = __expf(Mc - nm);
                d = d * fo + dc * fn;
                acc.x = acc.x * fo + ca.x * fn;
                acc.y = acc.y * fo + ca.y * fn;
                acc.z = acc.z * fo + ca.z * fn;
                acc.w = acc.w * fo + ca.w * fn;
                m = nm;
                #pragma unroll
                for (int j = 0; j < PT; ++j) x[j] = xn[j];
            }
        }
        if (act) {
            const float inv = 1.f / d;
            float4 o = make_float4(acc.x * inv, acc.y * inv, acc.z * inv, acc.w * inv);
            reinterpret_cast<float4*>(pooled + (size_t)b * EDIM)[t] = o;
        }
        __threadfence();      // release: pooled row visible before flag
        __syncthreads();
        if (t == 0) atomicExch(&g_flag[b], 1);
        return;
    }

    // ================= EXPERT ROLE (R9-proven 3xTF32 body) =================
    const int e = blockIdx.x - B;
    const int tiles_per_slab = 6 * mtiles;
    const int c = e / tiles_per_slab;
    const int rem = e % tiles_per_slab;
    const int mt = rem / 6;
    const int ntile = rem % 6;

    const bool dense = (c == NDOM);
    const int cnt = dense ? B : g_counts[c];
    if (mt * 64 >= cnt) return;

    const float* W    = dense ? Wsh : (Wsp + (size_t)c * EDIM * HDIM);
    const float* bias = dense ? bsh : (bsp + c * HDIM);
    const int colbase = ntile * 64;
    const int outcol  = (dense ? 0 : HDIM) + colbase;

    // wait until this tile's samples are pooled (acquire)
    if (t < 64) {
        const int amrow = mt * 64 + t;
        if (amrow < cnt) {
            const int s = dense ? amrow : g_idx[c * BMAX + amrow];
            while (((volatile int*)g_flag)[s] == 0) __nanosleep(64);
        }
    }
    __syncthreads();
    __threadfence();

    const int lane = t & 31, wid = t >> 5;
    const int warp_m = wid & 3, warp_n = wid >> 2;
    const int gid = lane >> 2, tig = lane & 3;

    const int arow = t >> 2, akk = (t & 3) * 4;
    const int bk = t >> 4, bn = (t & 15) * 4;

    int gi = -1;
    {
        const int amrow = mt * 64 + arow;
        if (amrow < cnt) gi = dense ? amrow : g_idx[c * BMAX + amrow];
    }
    const float* Ap = pooled + (size_t)(gi >= 0 ? gi : 0) * EDIM;

    float acc[4][4];
    #pragma unroll
    for (int i = 0; i < 4; ++i)
        #pragma unroll
        for (int j = 0; j < 4; ++j) acc[i][j] = 0.f;

    const int NS = EDIM / 16;
    float4 av = make_float4(0.f, 0.f, 0.f, 0.f);
    if (gi >= 0) av = *reinterpret_cast<const float4*>(Ap + akk);
    float4 bv = *reinterpret_cast<const float4*>(W + (size_t)bk * HDIM + colbase + bn);
    sm.g.As[0][akk + 0][arow] = av.x; sm.g.As[0][akk + 1][arow] = av.y;
    sm.g.As[0][akk + 2][arow] = av.z; sm.g.As[0][akk + 3][arow] = av.w;
    *reinterpret_cast<float4*>(&sm.g.Bs[0][bk][bn]) = bv;
    __syncthreads();

    const int am = warp_m * 16;
    const int bn0 = warp_n * 32;

    for (int s = 0; s < NS; ++s) {
        const int cur = s & 1;
        float4 av2 = make_float4(0.f, 0.f, 0.f, 0.f), bv2;
        if (s + 1 < NS) {
            const int k0 = (s + 1) * 16;
            if (gi >= 0) av2 = *reinterpret_cast<const float4*>(Ap + k0 + akk);
            bv2 = *reinterpret_cast<const float4*>(W + (size_t)(k0 + bk) * HDIM + colbase + bn);
        }

        #pragma unroll
        for (int g = 0; g < 2; ++g) {
            const int ka = g * 8;
            float a0 = sm.g.As[cur][ka + tig][am + gid];
            float a1 = sm.g.As[cur][ka + tig][am + gid + 8];
            float a2 = sm.g.As[cur][ka + tig + 4][am + gid];
            float a3 = sm.g.As[cur][ka + tig + 4][am + gid + 8];
            float ah0 = tf32_trunc(a0), al0 = tf32_trunc(a0 - ah0);
            float ah1 = tf32_trunc(a1), al1 = tf32_trunc(a1 - ah1);
            float ah2 = tf32_trunc(a2), al2 = tf32_trunc(a2 - ah2);
            float ah3 = tf32_trunc(a3), al3 = tf32_trunc(a3 - ah3);
            #pragma unroll
            for (int nt = 0; nt < 4; ++nt) {
                const int bcol = bn0 + nt * 8 + gid;
                float b0 = sm.g.Bs[cur][ka + tig][bcol];
                float b1 = sm.g.Bs[cur][ka + tig + 4][bcol];
                float bh0 = tf32_trunc(b0), bl0 = tf32_trunc(b0 - bh0);
                float bh1 = tf32_trunc(b1), bl1 = tf32_trunc(b1 - bh1);
                mma_tf32(acc[nt], ah0, ah1, ah2, ah3, bh0, bh1);
                mma_tf32(acc[nt], ah0, ah1, ah2, ah3, bl0, bl1);
                mma_tf32(acc[nt], al0, al1, al2, al3, bh0, bh1);
            }
        }

        if (s + 1 < NS) {
            const int nb = cur ^ 1;
            sm.g.As[nb][akk + 0][arow] = av2.x; sm.g.As[nb][akk + 1][arow] = av2.y;
            sm.g.As[nb][akk + 2][arow] = av2.z; sm.g.As[nb][akk + 3][arow] = av2.w;
            *reinterpret_cast<float4*>(&sm.g.Bs[nb][bk][bn]) = bv2;
        }
        __syncthreads();
    }

    const int r0 = mt * 64 + am + gid;
    const int r1 = r0 + 8;
    int ridx0 = 0, ridx1 = 0;
    const bool v0 = (r0 < cnt), v1 = (r1 < cnt);
    if (v0) ridx0 = dense ? r0 : g_idx[c * BMAX + r0];
    if (v1) ridx1 = dense ? r1 : g_idx[c * BMAX + r1];

    #pragma unroll
    for (int nt = 0; nt < 4; ++nt) {
        const int cn = bn0 + nt * 8 + 2 * tig;
        const float bb0 = bias[colbase + cn];
        const float bb1 = bias[colbase + cn + 1];
        if (v0) {
            float2 o;
            o.x = fmaxf(acc[nt][0] + bb0, 0.f);
            o.y = fmaxf(acc[nt][1] + bb1, 0.f);
            *reinterpret_cast<float2*>(&g_feature[(size_t)ridx0 * EDIM + outcol + cn]) = o;
        }
        if (v1) {
            float2 o;
            o.x = fmaxf(acc[nt][2] + bb0, 0.f);
            o.y = fmaxf(acc[nt][3] + bb1, 0.f);
            *reinterpret_cast<float2*>(&g_feature[(size_t)ridx1 * EDIM + outcol + cn]) = o;
        }
    }
}

// ---------------------------------------------------------------------------
// 64x64 double-buffered scalar GEMM tile device function (proven).
// ---------------------------------------------------------------------------
__device__ __forceinline__ void gemm64_tile(
    const float* __restrict__ A, int lda,
    const float* __restrict__ W, int ldw,
    const float* __restrict__ bias,
    float* __restrict__ C, int ldc,
    int M, int K, int mt, int colbase,
    float (*As)[16][68], float (*Bs)[16][64])
{
    const int t = threadIdx.x;
    const int arow = t >> 2, akk = (t & 3) * 4;
    const int bk = t >> 4, bn = (t & 15) * 4;
    const int ty = t >> 4, tx = t & 15;

    const int ga = mt * 64 + arow;
    const bool aload = (ga < M);
    const float* Ap = A + (size_t)(aload ? ga : 0) * lda;

    float acc[4][4];
    #pragma unroll
    for (int i = 0; i < 4; ++i)
        #pragma unroll
        for (int j = 0; j < 4; ++j) acc[i][j] = 0.f;

    const int NS = K / 16;
    float4 av = make_float4(0.f, 0.f, 0.f, 0.f);
    if (aload) av = *reinterpret_cast<const float4*>(Ap + akk);
    float4 bv = *reinterpret_cast<const float4*>(W + (size_t)bk * ldw + colbase + bn);
    As[0][akk + 0][arow] = av.x; As[0][akk + 1][arow] = av.y;
    As[0][akk + 2][arow] = av.z; As[0][akk + 3][arow] = av.w;
    *reinterpret_cast<float4*>(&Bs[0][bk][bn]) = bv;
    __syncthreads();

    for (int s = 0; s < NS; ++s) {
        const int cur = s & 1;
        float4 av2 = make_float4(0.f, 0.f, 0.f, 0.f), bv2;
        if (s + 1 < NS) {
            const int k0 = (s + 1) * 16;
            if (aload) av2 = *reinterpret_cast<const float4*>(Ap + k0 + akk);
            bv2 = *reinterpret_cast<const float4*>(W + (size_t)(k0 + bk) * ldw + colbase + bn);
        }
        #pragma unroll
        for (int kk = 0; kk < 16; ++kk) {
            float4 a4 = *reinterpret_cast<const float4*>(&As[cur][kk][ty * 4]);
            float4 b4 = *reinterpret_cast<const float4*>(&Bs[cur][kk][tx * 4]);
            float ar[4] = {a4.x, a4.y, a4.z, a4.w};
            float br[4] = {b4.x, b4.y, b4.z, b4.w};
            #pragma unroll
            for (int i = 0; i < 4; ++i)
                #pragma unroll
                for (int j = 0; j < 4; ++j) acc[i][j] += ar[i] * br[j];
        }
        if (s + 1 < NS) {
            const int nb = cur ^ 1;
            As[nb][akk + 0][arow] = av2.x; As[nb][akk + 1][arow] = av2.y;
            As[nb][akk + 2][arow] = av2.z; As[nb][akk + 3][arow] = av2.w;
            *reinterpret_cast<float4*>(&Bs[nb][bk][bn]) = bv2;
        }
        __syncthreads();
    }

    float4 bb4 = *reinterpret_cast<const float4*>(bias + colbase + tx * 4);
    float bb[4] = {bb4.x, bb4.y, bb4.z, bb4.w};
    #pragma unroll
    for (int i = 0; i < 4; ++i) {
        const int row = mt * 64 + ty * 4 + i;
        if (row < M) {
            float4 o;
            o.x = fmaxf(acc[i][0] + bb[0], 0.f);
            o.y = fmaxf(acc[i][1] + bb[1], 0.f);
            o.z = fmaxf(acc[i][2] + bb[2], 0.f);
            o.w = fmaxf(acc[i][3] + bb[3], 0.f);
            *reinterpret_cast<float4*>(C + (size_t)row * ldc + colbase + tx * 4) = o;
        }
    }
}

// ---------------------------------------------------------------------------
// fusedA: dec1 (32 tiles) + domain1 (192 tiles) + cls (warp/sample)
// ---------------------------------------------------------------------------
#define FA_DEC1 32
#define FA_DOM1 (FA_DEC1 + 192)
__global__ void __launch_bounds__(256) fusedA_kernel(
    const float* __restrict__ Wd1, const float* __restrict__ bd1,
    const float* __restrict__ Wdo1, const float* __restrict__ bdo1,
    const float* __restrict__ Wc, const float* __restrict__ bc,
    float* __restrict__ out, int B)
{
    __shared__ float As[2][16][68];
    __shared__ float Bs[2][16][64];
    const int bx = blockIdx.x;

    if (bx < FA_DEC1) {
        gemm64_tile(g_feature, EDIM, Wd1, 64, bd1, g_h1, 64, B, EDIM, bx, 0, As, Bs);
    } else if (bx < FA_DOM1) {
        const int idx = bx - FA_DEC1;
        gemm64_tile(g_feature, EDIM, Wdo1, HDIM, bdo1, g_hdom, HDIM, B, HDIM,
                    idx / 6, (idx % 6) * 64, As, Bs);
    } else {
        const int sample = (bx - FA_DOM1) * 8 + (threadIdx.x >> 5);
        const int lane = threadIdx.x & 31;
        if (sample < B) {
            const float4* f = reinterpret_cast<const float4*>(g_feature + (size_t)sample * EDIM);
            const float4* wc = reinterpret_cast<const float4*>(Wc);
            float acc = 0.f;
            #pragma unroll
            for (int i = 0; i < 6; ++i) {
                float4 a = f[lane + 32 * i], ww = wc[lane + 32 * i];
                acc += a.x * ww.x + a.y * ww.y + a.z * ww.z + a.w * ww.w;
            }
            #pragma unroll
            for (int o = 16; o; o >>= 1) acc += __shfl_xor_sync(0xffffffffu, acc, o);
            if (lane == 0) out[sample] = 1.f / (1.f + __expf(-(acc + bc[0])));
        }
    }
}

// ---------------------------------------------------------------------------
// fusedB: dec2 (384 tiles) + domain2 (warp/sample)
// ---------------------------------------------------------------------------
#define FB_DEC2 384
__global__ void __launch_bounds__(256) fusedB_kernel(
    const float* __restrict__ Wd2, const float* __restrict__ bd2,
    const float* __restrict__ Wdo2, const float* __restrict__ bdo2,
    float* __restrict__ rec, float* __restrict__ dp, int B)
{
    __shared__ float As[2][16][68];
    __shared__ float Bs[2][16][64];
    const int bx = blockIdx.x;

    if (bx < FB_DEC2) {
        gemm64_tile(g_h1, 64, Wd2, EDIM, bd2, rec, EDIM, B, 64,
                    bx / 12, (bx % 12) * 64, As, Bs);
    } else {
        const int sample = (bx - FB_DEC2) * 8 + (threadIdx.x >> 5);
        const int lane = threadIdx.x & 31;
        if (sample < B) {
            const float* h = g_hdom + (size_t)sample * HDIM;
            float a[NDOM];
            #pragma unroll
            for (int j = 0; j < NDOM; ++j) a[j] = 0.f;
            #pragma unroll
            for (int i = 0; i < 3; ++i) {
                const int k = (lane + 32 * i) * 4;
                float4 hv = *reinterpret_cast<const float4*>(h + k);
                float hh[4] = {hv.x, hv.y, hv.z, hv.w};
                #pragma unroll
                for (int q = 0; q < 4; ++q) {
                    const float* wrow = Wdo2 + (k + q) * NDOM;
                    #pragma unroll
                    for (int j = 0; j < NDOM; ++j) a[j] += hh[q] * wrow[j];
                }
            }
            #pragma unroll
            for (int j = 0; j < NDOM; ++j) {
                #pragma unroll
                for (int o = 16; o; o >>= 1) a[j] += __shfl_xor_sync(0xffffffffu, a[j], o);
            }
            if (lane == 0) {
                #pragma unroll
                for (int j = 0; j < NDOM; ++j)
                    dp[(size_t)sample * NDOM + j] = a[j] + bdo2[j];
            }
        }
    }
}

// ---------------------------------------------------------------------------
extern "C" void kernel_launch(void* const* d_in, const int* in_sizes, int n_in,
                              void* d_out, int out_size)
{
    const float* bert     = (const float*)d_in[0];
    const int*   masks    = (const int*)d_in[1];
    const int*   category = (const int*)d_in[2];
    const float* att_w = (const float*)d_in[4];
    const float* att_b = (const float*)d_in[5];
    const float* Wsh = (const float*)d_in[6];  const float* bsh = (const float*)d_in[7];
    const float* Wsp = (const float*)d_in[8];  const float* bsp = (const float*)d_in[9];
    const float* Wd1 = (const float*)d_in[10]; const float* bd1 = (const float*)d_in[11];
    const float* Wd2 = (const float*)d_in[12]; const float* bd2 = (const float*)d_in[13];
    const float* Wc  = (const float*)d_in[14]; const float* bc  = (const float*)d_in[15];
    const float* Wdo1 = (const float*)d_in[16]; const float* bdo1 = (const float*)d_in[17];
    const float* Wdo2 = (const float*)d_in[18]; const float* bdo2 = (const float*)d_in[19];

    const int B = in_sizes[2];

    float* out    = (float*)d_out;
    float* rec    = out + B;
    float* pooled = rec + (size_t)B * EDIM;
    float* dp     = pooled + (size_t)B * EDIM;

    // flags + routing lists (stream-ordered before the fused kernel)
    zero_kernel<<<(B + 255) / 256, 256>>>(B);
    scatter_kernel<<<(B + 255) / 256, 256>>>(category, B);

    // fused pool + expert/shared MLP (expert overlaps the pool tail)
    const int mtiles = (B + 63) / 64;
    const int expert_blocks = (NDOM + 1) * 6 * mtiles;
    fused_pool_expert_kernel<<<B + expert_blocks, 256>>>(
        bert, masks, att_w, att_b, pooled, Wsh, bsh, Wsp, bsp, B, mtiles);

    // fusedA: dec1 + domain1 + cls (all read g_feature)
    fusedA_kernel<<<FA_DOM1 + (B + 7) / 8, 256>>>(
        Wd1, bd1, Wdo1, bdo1, Wc, bc, out, B);

    // fusedB: dec2 + domain2
    fusedB_kernel<<<FB_DEC2 + (B + 7) / 8, 256>>>(
        Wd2, bd2, Wdo2, bdo2, rec, dp, B);
}

// round 11
// speedup vs baseline: 1.0871x; 1.0871x over previous
#include <cuda_runtime.h>
#include <math.h>

#define LSEQ 256
#define EDIM 768
#define HDIM 384
#define NDOM 9
#define BMAX 2048
#define PT 8

// device scratch (no allocation allowed)
__device__ float g_feature[(size_t)BMAX * EDIM];   // [B, 2H]: [shared | specific]
__device__ float g_h1[(size_t)BMAX * 64];
__device__ float g_hdom[(size_t)BMAX * HDIM];
__device__ int   g_counts[16];
__device__ int   g_idx[NDOM * BMAX];

// ---------------------------------------------------------------------------
// K1: fused masked-attention pooling, chunked online softmax (proven).
// ---------------------------------------------------------------------------
__global__ void __launch_bounds__(192) pool_kernel(
    const float* __restrict__ bert, const int* __restrict__ masks,
    const float* __restrict__ att_w, const float* __restrict__ att_b,
    float* __restrict__ pooled)
{
    const int b = blockIdx.x, tid = threadIdx.x;
    const int lane = tid & 31, wid = tid >> 5;
    const float4* base = reinterpret_cast<const float4*>(bert + (size_t)b * LSEQ * EDIM);
    const float4 w = reinterpret_cast<const float4*>(att_w)[tid];
    const float bb = att_b[0];

    __shared__ float wr[2][PT][8];
    __shared__ int msk[LSEQ];
    for (int i = tid; i < LSEQ; i += 192) msk[i] = masks[b * LSEQ + i];

    float4 acc = make_float4(0.f, 0.f, 0.f, 0.f);
    float m = -3e38f, d = 0.f;

    float4 x[PT], xn[PT];
    #pragma unroll
    for (int j = 0; j < PT; ++j) x[j] = base[j * 192 + tid];
    __syncthreads();

    const int NC = LSEQ / PT;
    for (int c = 0; c < NC; ++c) {
        const int cb = c & 1;
        float p[PT];
        #pragma unroll
        for (int j = 0; j < PT; ++j)
            p[j] = x[j].x * w.x + x[j].y * w.y + x[j].z * w.z + x[j].w * w.w;

        if (c + 1 < NC) {
            #pragma unroll
            for (int j = 0; j < PT; ++j)
                xn[j] = base[((c + 1) * PT + j) * 192 + tid];
        }

        #pragma unroll
        for (int j = 0; j < PT; ++j) {
            #pragma unroll
            for (int o = 16; o; o >>= 1)
                p[j] += __shfl_xor_sync(0xffffffffu, p[j], o);
        }
        if (lane == 0) {
            #pragma unroll
            for (int j = 0; j < PT; ++j) wr[cb][j][wid] = p[j];
        }
        __syncthreads();

        float s[PT], Mc = -3e38f;
        #pragma unroll
        for (int j = 0; j < PT; ++j) {
            s[j] = wr[cb][j][0] + wr[cb][j][1] + wr[cb][j][2]
                 + wr[cb][j][3] + wr[cb][j][4] + wr[cb][j][5] + bb;
            if (msk[c * PT + j] == 0) s[j] = -1e9f;
            Mc = fmaxf(Mc, s[j]);
        }
        float pe[PT], dc = 0.f;
        #pragma unroll
        for (int j = 0; j < PT; ++j) { pe[j] = __expf(s[j] - Mc); dc += pe[j]; }
        float4 ca = make_float4(0.f, 0.f, 0.f, 0.f);
        #pragma unroll
        for (int j = 0; j < PT; ++j) {
            ca.x += pe[j] * x[j].x; ca.y += pe[j] * x[j].y;
            ca.z += pe[j] * x[j].z; ca.w += pe[j] * x[j].w;
        }
        const float nm = fmaxf(m, Mc);
        const float fo = __expf(m - nm), fn = __expf(Mc - nm);
        d = d * fo + dc * fn;
        acc.x = acc.x * fo + ca.x * fn;
        acc.y = acc.y * fo + ca.y * fn;
        acc.z = acc.z * fo + ca.z * fn;
        acc.w = acc.w * fo + ca.w * fn;
        m = nm;
        #pragma unroll
        for (int j = 0; j < PT; ++j) x[j] = xn[j];
    }
    const float inv = 1.f / d;
    float4 o = make_float4(acc.x * inv, acc.y * inv, acc.z * inv, acc.w * inv);
    reinterpret_cast<float4*>(pooled + (size_t)b * EDIM)[tid] = o;
}

// ---------------------------------------------------------------------------
// category routing lists
// ---------------------------------------------------------------------------
__global__ void zero_counts_kernel() { if (threadIdx.x < 16) g_counts[threadIdx.x] = 0; }

__global__ void scatter_kernel(const int* __restrict__ category, int B) {
    int i = blockIdx.x * blockDim.x + threadIdx.x;
    if (i < B) {
        int c = category[i];
        int p = atomicAdd(&g_counts[c], 1);
        g_idx[c * BMAX + p] = i;
    }
}

// ---------------------------------------------------------------------------
// tf32 helpers (3xTF32 compensated; numerics proven: rel_err ~6e-6)
// ---------------------------------------------------------------------------
__device__ __forceinline__ float tf32_trunc(float v) {
    return __uint_as_float(__float_as_uint(v) & 0xFFFFE000u);
}

__device__ __forceinline__ void mma_tf32(float* c,
    float a0, float a1, float a2, float a3, float b0, float b1)
{
    asm volatile(
        "mma.sync.aligned.m16n8k8.row.col.f32.tf32.tf32.f32 "
        "{%0,%1,%2,%3}, {%4,%5,%6,%7}, {%8,%9}, {%0,%1,%2,%3};\n"
        : "+f"(c[0]), "+f"(c[1]), "+f"(c[2]), "+f"(c[3])
        : "r"(__float_as_uint(a0)), "r"(__float_as_uint(a1)),
          "r"(__float_as_uint(a2)), "r"(__float_as_uint(a3)),
          "r"(__float_as_uint(b0)), "r"(__float_as_uint(b1)));
}

// ---------------------------------------------------------------------------
// Generic DENSE 64x64 3xTF32 GEMM tile (expert body minus gather).
// C = relu(A[M,K] @ W[K,N] + bias), K%16==0, colbase+64 <= N.
// smem: As/Bs [2][16][68] fp32, double-buffered, one sync per K-step.
// ---------------------------------------------------------------------------
__device__ __forceinline__ void mma_gemm64_tile(
    const float* __restrict__ A, int lda,
    const float* __restrict__ W, int ldw,
    const float* __restrict__ bias,
    float* __restrict__ C, int ldc,
    int M, int K, int mt, int colbase,
    float (*As)[16][68], float (*Bs)[16][68])
{
    const int t = threadIdx.x;
    const int lane = t & 31, wid = t >> 5;
    const int warp_m = wid & 3, warp_n = wid >> 2;
    const int gid = lane >> 2, tig = lane & 3;

    const int arow = t >> 2, akk = (t & 3) * 4;
    const int bk = t >> 4, bn = (t & 15) * 4;

    const int ga = mt * 64 + arow;
    const bool aload = (ga < M);
    const float* Ap = A + (size_t)(aload ? ga : 0) * lda;

    float acc[4][4];
    #pragma unroll
    for (int i = 0; i < 4; ++i)
        #pragma unroll
        for (int j = 0; j < 4; ++j) acc[i][j] = 0.f;

    const int NS = K / 16;
    float4 av = make_float4(0.f, 0.f, 0.f, 0.f);
    if (aload) av = *reinterpret_cast<const float4*>(Ap + akk);
    float4 bv = *reinterpret_cast<const float4*>(W + (size_t)bk * ldw + colbase + bn);
    As[0][akk + 0][arow] = av.x; As[0][akk + 1][arow] = av.y;
    As[0][akk + 2][arow] = av.z; As[0][akk + 3][arow] = av.w;
    *reinterpret_cast<float4*>(&Bs[0][bk][bn]) = bv;
    __syncthreads();

    const int am = warp_m * 16;
    const int bn0 = warp_n * 32;

    for (int s = 0; s < NS; ++s) {
        const int cur = s & 1;
        float4 av2 = make_float4(0.f, 0.f, 0.f, 0.f), bv2;
        if (s + 1 < NS) {
            const int k0 = (s + 1) * 16;
            if (aload) av2 = *reinterpret_cast<const float4*>(Ap + k0 + akk);
            bv2 = *reinterpret_cast<const float4*>(W + (size_t)(k0 + bk) * ldw + colbase + bn);
        }

        #pragma unroll
        for (int g = 0; g < 2; ++g) {
            const int ka = g * 8;
            float a0 = As[cur][ka + tig][am + gid];
            float a1 = As[cur][ka + tig][am + gid + 8];
            float a2 = As[cur][ka + tig + 4][am + gid];
            float a3 = As[cur][ka + tig + 4][am + gid + 8];
            float ah0 = tf32_trunc(a0), al0 = tf32_trunc(a0 - ah0);
            float ah1 = tf32_trunc(a1), al1 = tf32_trunc(a1 - ah1);
            float ah2 = tf32_trunc(a2), al2 = tf32_trunc(a2 - ah2);
            float ah3 = tf32_trunc(a3), al3 = tf32_trunc(a3 - ah3);
            #pragma unroll
            for (int nt = 0; nt < 4; ++nt) {
                const int bcol = bn0 + nt * 8 + gid;
                float b0 = Bs[cur][ka + tig][bcol];
                float b1 = Bs[cur][ka + tig + 4][bcol];
                float bh0 = tf32_trunc(b0), bl0 = tf32_trunc(b0 - bh0);
                float bh1 = tf32_trunc(b1), bl1 = tf32_trunc(b1 - bh1);
                mma_tf32(acc[nt], ah0, ah1, ah2, ah3, bh0, bh1);
                mma_tf32(acc[nt], ah0, ah1, ah2, ah3, bl0, bl1);
                mma_tf32(acc[nt], al0, al1, al2, al3, bh0, bh1);
            }
        }

        if (s + 1 < NS) {
            const int nb = cur ^ 1;
            As[nb][akk + 0][arow] = av2.x; As[nb][akk + 1][arow] = av2.y;
            As[nb][akk + 2][arow] = av2.z; As[nb][akk + 3][arow] = av2.w;
            *reinterpret_cast<float4*>(&Bs[nb][bk][bn]) = bv2;
        }
        __syncthreads();
    }

    const int r0 = mt * 64 + am + gid;
    const int r1 = r0 + 8;
    #pragma unroll
    for (int nt = 0; nt < 4; ++nt) {
        const int cn = bn0 + nt * 8 + 2 * tig;
        const float bb0 = bias[colbase + cn];
        const float bb1 = bias[colbase + cn + 1];
        if (r0 < M) {
            float2 o;
            o.x = fmaxf(acc[nt][0] + bb0, 0.f);
            o.y = fmaxf(acc[nt][1] + bb1, 0.f);
            *reinterpret_cast<float2*>(&C[(size_t)r0 * ldc + colbase + cn]) = o;
        }
        if (r1 < M) {
            float2 o;
            o.x = fmaxf(acc[nt][2] + bb0, 0.f);
            o.y = fmaxf(acc[nt][3] + bb1, 0.f);
            *reinterpret_cast<float2*>(&C[(size_t)r1 * ldc + colbase + cn]) = o;
        }
    }
}

// ---------------------------------------------------------------------------
// Expert + shared MLP, 3xTF32 (R9-proven, byte-identical).
// ---------------------------------------------------------------------------
__global__ void __launch_bounds__(256) expert_mma_kernel(
    const float* __restrict__ pooled,
    const float* __restrict__ Wsh, const float* __restrict__ bsh,
    const float* __restrict__ Wsp, const float* __restrict__ bsp,
    int B)
{
    const int c = blockIdx.z;
    const bool dense = (c == NDOM);
    const int cnt = dense ? B : g_counts[c];
    const int mt = blockIdx.y;
    if (mt * 64 >= cnt) return;

    const float* W    = dense ? Wsh : (Wsp + (size_t)c * EDIM * HDIM);
    const float* bias = dense ? bsh : (bsp + c * HDIM);
    const int colbase = blockIdx.x * 64;
    const int outcol  = (dense ? 0 : HDIM) + colbase;

    __shared__ float As[2][16][68];
    __shared__ float Bs[2][16][68];

    const int t = threadIdx.x;
    const int lane = t & 31, wid = t >> 5;
    const int warp_m = wid & 3, warp_n = wid >> 2;
    const int gid = lane >> 2, tig = lane & 3;

    const int arow = t >> 2, akk = (t & 3) * 4;
    const int bk = t >> 4, bn = (t & 15) * 4;

    int gi = -1;
    {
        const int amrow = mt * 64 + arow;
        if (amrow < cnt) gi = dense ? amrow : g_idx[c * BMAX + amrow];
    }
    const float* Ap = pooled + (size_t)(gi >= 0 ? gi : 0) * EDIM;

    float acc[4][4];
    #pragma unroll
    for (int i = 0; i < 4; ++i)
        #pragma unroll
        for (int j = 0; j < 4; ++j) acc[i][j] = 0.f;

    const int NS = EDIM / 16;
    float4 av = make_float4(0.f, 0.f, 0.f, 0.f);
    if (gi >= 0) av = *reinterpret_cast<const float4*>(Ap + akk);
    float4 bv = *reinterpret_cast<const float4*>(W + (size_t)bk * HDIM + colbase + bn);
    As[0][akk + 0][arow] = av.x; As[0][akk + 1][arow] = av.y;
    As[0][akk + 2][arow] = av.z; As[0][akk + 3][arow] = av.w;
    *reinterpret_cast<float4*>(&Bs[0][bk][bn]) = bv;
    __syncthreads();

    const int am = warp_m * 16;
    const int bn0 = warp_n * 32;

    for (int s = 0; s < NS; ++s) {
        const int cur = s & 1;
        float4 av2 = make_float4(0.f, 0.f, 0.f, 0.f), bv2;
        if (s + 1 < NS) {
            const int k0 = (s + 1) * 16;
            if (gi >= 0) av2 = *reinterpret_cast<const float4*>(Ap + k0 + akk);
            bv2 = *reinterpret_cast<const float4*>(W + (size_t)(k0 + bk) * HDIM + colbase + bn);
        }

        #pragma unroll
        for (int g = 0; g < 2; ++g) {
            const int ka = g * 8;
            float a0 = As[cur][ka + tig][am + gid];
            float a1 = As[cur][ka + tig][am + gid + 8];
            float a2 = As[cur][ka + tig + 4][am + gid];
            float a3 = As[cur][ka + tig + 4][am + gid + 8];
            float ah0 = tf32_trunc(a0), al0 = tf32_trunc(a0 - ah0);
            float ah1 = tf32_trunc(a1), al1 = tf32_trunc(a1 - ah1);
            float ah2 = tf32_trunc(a2), al2 = tf32_trunc(a2 - ah2);
            float ah3 = tf32_trunc(a3), al3 = tf32_trunc(a3 - ah3);
            #pragma unroll
            for (int nt = 0; nt < 4; ++nt) {
                const int bcol = bn0 + nt * 8 + gid;
                float b0 = Bs[cur][ka + tig][bcol];
                float b1 = Bs[cur][ka + tig + 4][bcol];
                float bh0 = tf32_trunc(b0), bl0 = tf32_trunc(b0 - bh0);
                float bh1 = tf32_trunc(b1), bl1 = tf32_trunc(b1 - bh1);
                mma_tf32(acc[nt], ah0, ah1, ah2, ah3, bh0, bh1);
                mma_tf32(acc[nt], ah0, ah1, ah2, ah3, bl0, bl1);
                mma_tf32(acc[nt], al0, al1, al2, al3, bh0, bh1);
            }
        }

        if (s + 1 < NS) {
            const int nb = cur ^ 1;
            As[nb][akk + 0][arow] = av2.x; As[nb][akk + 1][arow] = av2.y;
            As[nb][akk + 2][arow] = av2.z; As[nb][akk + 3][arow] = av2.w;
            *reinterpret_cast<float4*>(&Bs[nb][bk][bn]) = bv2;
        }
        __syncthreads();
    }

    const int r0 = mt * 64 + am + gid;
    const int r1 = r0 + 8;
    int ridx0 = 0, ridx1 = 0;
    const bool v0 = (r0 < cnt), v1 = (r1 < cnt);
    if (v0) ridx0 = dense ? r0 : g_idx[c * BMAX + r0];
    if (v1) ridx1 = dense ? r1 : g_idx[c * BMAX + r1];

    #pragma unroll
    for (int nt = 0; nt < 4; ++nt) {
        const int cn = bn0 + nt * 8 + 2 * tig;
        const float bb0 = bias[colbase + cn];
        const float bb1 = bias[colbase + cn + 1];
        if (v0) {
            float2 o;
            o.x = fmaxf(acc[nt][0] + bb0, 0.f);
            o.y = fmaxf(acc[nt][1] + bb1, 0.f);
            *reinterpret_cast<float2*>(&g_feature[(size_t)ridx0 * EDIM + outcol + cn]) = o;
        }
        if (v1) {
            float2 o;
            o.x = fmaxf(acc[nt][2] + bb0, 0.f);
            o.y = fmaxf(acc[nt][3] + bb1, 0.f);
            *reinterpret_cast<float2*>(&g_feature[(size_t)ridx1 * EDIM + outcol + cn]) = o;
        }
    }
}

// ---------------------------------------------------------------------------
// fusedA: dec1 (32 mma tiles) + domain1 (192 mma tiles) + cls (warp/sample)
// ---------------------------------------------------------------------------
#define FA_DEC1 32
#define FA_DOM1 (FA_DEC1 + 192)
__global__ void __launch_bounds__(256) fusedA_kernel(
    const float* __restrict__ Wd1, const float* __restrict__ bd1,
    const float* __restrict__ Wdo1, const float* __restrict__ bdo1,
    const float* __restrict__ Wc, const float* __restrict__ bc,
    float* __restrict__ out, int B)
{
    __shared__ float As[2][16][68];
    __shared__ float Bs[2][16][68];
    const int bx = blockIdx.x;

    if (bx < FA_DEC1) {
        // dec1: [B,768] @ [768,64] -> g_h1
        mma_gemm64_tile(g_feature, EDIM, Wd1, 64, bd1, g_h1, 64, B, EDIM,
                        bx, 0, As, Bs);
    } else if (bx < FA_DOM1) {
        // domain1: [B,384] @ [384,384] -> g_hdom (A = shared half)
        const int idx = bx - FA_DEC1;
        mma_gemm64_tile(g_feature, EDIM, Wdo1, HDIM, bdo1, g_hdom, HDIM, B, HDIM,
                        idx / 6, (idx % 6) * 64, As, Bs);
    } else {
        const int sample = (bx - FA_DOM1) * 8 + (threadIdx.x >> 5);
        const int lane = threadIdx.x & 31;
        if (sample < B) {
            const float4* f = reinterpret_cast<const float4*>(g_feature + (size_t)sample * EDIM);
            const float4* wc = reinterpret_cast<const float4*>(Wc);
            float acc = 0.f;
            #pragma unroll
            for (int i = 0; i < 6; ++i) {
                float4 a = f[lane + 32 * i], ww = wc[lane + 32 * i];
                acc += a.x * ww.x + a.y * ww.y + a.z * ww.z + a.w * ww.w;
            }
            #pragma unroll
            for (int o = 16; o; o >>= 1) acc += __shfl_xor_sync(0xffffffffu, acc, o);
            if (lane == 0) out[sample] = 1.f / (1.f + __expf(-(acc + bc[0])));
        }
    }
}

// ---------------------------------------------------------------------------
// fusedB: dec2 (384 mma tiles) + domain2 (warp/sample)
// ---------------------------------------------------------------------------
#define FB_DEC2 384
__global__ void __launch_bounds__(256) fusedB_kernel(
    const float* __restrict__ Wd2, const float* __restrict__ bd2,
    const float* __restrict__ Wdo2, const float* __restrict__ bdo2,
    float* __restrict__ rec, float* __restrict__ dp, int B)
{
    __shared__ float As[2][16][68];
    __shared__ float Bs[2][16][68];
    const int bx = blockIdx.x;

    if (bx < FB_DEC2) {
        // dec2: [B,64] @ [64,768] -> rec ; 12 coltiles x 32 mtiles
        mma_gemm64_tile(g_h1, 64, Wd2, EDIM, bd2, rec, EDIM, B, 64,
                        bx / 12, (bx % 12) * 64, As, Bs);
    } else {
        const int sample = (bx - FB_DEC2) * 8 + (threadIdx.x >> 5);
        const int lane = threadIdx.x & 31;
        if (sample < B) {
            const float* h = g_hdom + (size_t)sample * HDIM;
            float a[NDOM];
            #pragma unroll
            for (int j = 0; j < NDOM; ++j) a[j] = 0.f;
            #pragma unroll
            for (int i = 0; i < 3; ++i) {
                const int k = (lane + 32 * i) * 4;
                float4 hv = *reinterpret_cast<const float4*>(h + k);
                float hh[4] = {hv.x, hv.y, hv.z, hv.w};
                #pragma unroll
                for (int q = 0; q < 4; ++q) {
                    const float* wrow = Wdo2 + (k + q) * NDOM;
                    #pragma unroll
                    for (int j = 0; j < NDOM; ++j) a[j] += hh[q] * wrow[j];
                }
            }
            #pragma unroll
            for (int j = 0; j < NDOM; ++j) {
                #pragma unroll
                for (int o = 16; o; o >>= 1) a[j] += __shfl_xor_sync(0xffffffffu, a[j], o);
            }
            if (lane == 0) {
                #pragma unroll
                for (int j = 0; j < NDOM; ++j)
                    dp[(size_t)sample * NDOM + j] = a[j] + bdo2[j];
            }
        }
    }
}

// ---------------------------------------------------------------------------
extern "C" void kernel_launch(void* const* d_in, const int* in_sizes, int n_in,
                              void* d_out, int out_size)
{
    const float* bert     = (const float*)d_in[0];
    const int*   masks    = (const int*)d_in[1];
    const int*   category = (const int*)d_in[2];
    const float* att_w = (const float*)d_in[4];
    const float* att_b = (const float*)d_in[5];
    const float* Wsh = (const float*)d_in[6];  const float* bsh = (const float*)d_in[7];
    const float* Wsp = (const float*)d_in[8];  const float* bsp = (const float*)d_in[9];
    const float* Wd1 = (const float*)d_in[10]; const float* bd1 = (const float*)d_in[11];
    const float* Wd2 = (const float*)d_in[12]; const float* bd2 = (const float*)d_in[13];
    const float* Wc  = (const float*)d_in[14]; const float* bc  = (const float*)d_in[15];
    const float* Wdo1 = (const float*)d_in[16]; const float* bdo1 = (const float*)d_in[17];
    const float* Wdo2 = (const float*)d_in[18]; const float* bdo2 = (const float*)d_in[19];

    const int B = in_sizes[2];

    float* out    = (float*)d_out;
    float* rec    = out + B;
    float* pooled = rec + (size_t)B * EDIM;
    float* dp     = pooled + (size_t)B * EDIM;

    // routing lists (off the data critical path)
    zero_counts_kernel<<<1, 16>>>();
    scatter_kernel<<<(B + 255) / 256, 256>>>(category, B);

    pool_kernel<<<B, 192>>>(bert, masks, att_w, att_b, pooled);

    // shared MLP (slab 9) + 9 specific experts: 3xTF32 tensor cores
    expert_mma_kernel<<<dim3(HDIM / 64, (B + 63) / 64, NDOM + 1), 256>>>(
        pooled, Wsh, bsh, Wsp, bsp, B);

    // fusedA: dec1 + domain1 + cls (all read g_feature)
    fusedA_kernel<<<FA_DOM1 + (B + 7) / 8, 256>>>(
        Wd1, bd1, Wdo1, bdo1, Wc, bc, out, B);

    // fusedB: dec2 + domain2
    fusedB_kernel<<<FB_DEC2 + (B + 7) / 8, 256>>>(
        Wd2, bd2, Wdo2, bdo2, rec, dp, B);
}

// round 12
// speedup vs baseline: 1.0872x; 1.0001x over previous
#include <cuda_runtime.h>
#include <math.h>

#define LSEQ 256
#define EDIM 768
#define HDIM 384
#define NDOM 9
#define BMAX 2048
#define PT 8

// device scratch (no allocation allowed)
__device__ float g_feature[(size_t)BMAX * EDIM];   // [B, 2H]: [shared | specific]
__device__ float g_h1[(size_t)BMAX * 64];
__device__ float g_hdom[(size_t)BMAX * HDIM];
__device__ int   g_counts[16];
__device__ int   g_idx[NDOM * BMAX];

// ---------------------------------------------------------------------------
// K1: fused masked-attention pooling, chunked online softmax (proven).
// ---------------------------------------------------------------------------
__global__ void __launch_bounds__(192) pool_kernel(
    const float* __restrict__ bert, const int* __restrict__ masks,
    const float* __restrict__ att_w, const float* __restrict__ att_b,
    float* __restrict__ pooled)
{
    const int b = blockIdx.x, tid = threadIdx.x;
    const int lane = tid & 31, wid = tid >> 5;
    const float4* base = reinterpret_cast<const float4*>(bert + (size_t)b * LSEQ * EDIM);
    const float4 w = reinterpret_cast<const float4*>(att_w)[tid];
    const float bb = att_b[0];

    __shared__ float wr[2][PT][8];
    __shared__ int msk[LSEQ];
    for (int i = tid; i < LSEQ; i += 192) msk[i] = masks[b * LSEQ + i];

    float4 acc = make_float4(0.f, 0.f, 0.f, 0.f);
    float m = -3e38f, d = 0.f;

    float4 x[PT], xn[PT];
    #pragma unroll
    for (int j = 0; j < PT; ++j) x[j] = base[j * 192 + tid];
    __syncthreads();

    const int NC = LSEQ / PT;
    for (int c = 0; c < NC; ++c) {
        const int cb = c & 1;
        float p[PT];
        #pragma unroll
        for (int j = 0; j < PT; ++j)
            p[j] = x[j].x * w.x + x[j].y * w.y + x[j].z * w.z + x[j].w * w.w;

        if (c + 1 < NC) {
            #pragma unroll
            for (int j = 0; j < PT; ++j)
                xn[j] = base[((c + 1) * PT + j) * 192 + tid];
        }

        #pragma unroll
        for (int j = 0; j < PT; ++j) {
            #pragma unroll
            for (int o = 16; o; o >>= 1)
                p[j] += __shfl_xor_sync(0xffffffffu, p[j], o);
        }
        if (lane == 0) {
            #pragma unroll
            for (int j = 0; j < PT; ++j) wr[cb][j][wid] = p[j];
        }
        __syncthreads();

        float s[PT], Mc = -3e38f;
        #pragma unroll
        for (int j = 0; j < PT; ++j) {
            s[j] = wr[cb][j][0] + wr[cb][j][1] + wr[cb][j][2]
                 + wr[cb][j][3] + wr[cb][j][4] + wr[cb][j][5] + bb;
            if (msk[c * PT + j] == 0) s[j] = -1e9f;
            Mc = fmaxf(Mc, s[j]);
        }
        float pe[PT], dc = 0.f;
        #pragma unroll
        for (int j = 0; j < PT; ++j) { pe[j] = __expf(s[j] - Mc); dc += pe[j]; }
        float4 ca = make_float4(0.f, 0.f, 0.f, 0.f);
        #pragma unroll
        for (int j = 0; j < PT; ++j) {
            ca.x += pe[j] * x[j].x; ca.y += pe[j] * x[j].y;
            ca.z += pe[j] * x[j].z; ca.w += pe[j] * x[j].w;
        }
        const float nm = fmaxf(m, Mc);
        const float fo = __expf(m - nm), fn = __expf(Mc - nm);
        d = d * fo + dc * fn;
        acc.x = acc.x * fo + ca.x * fn;
        acc.y = acc.y * fo + ca.y * fn;
        acc.z = acc.z * fo + ca.z * fn;
        acc.w = acc.w * fo + ca.w * fn;
        m = nm;
        #pragma unroll
        for (int j = 0; j < PT; ++j) x[j] = xn[j];
    }
    const float inv = 1.f / d;
    float4 o = make_float4(acc.x * inv, acc.y * inv, acc.z * inv, acc.w * inv);
    reinterpret_cast<float4*>(pooled + (size_t)b * EDIM)[tid] = o;
}

// ---------------------------------------------------------------------------
// category routing lists
// ---------------------------------------------------------------------------
__global__ void zero_counts_kernel() { if (threadIdx.x < 16) g_counts[threadIdx.x] = 0; }

__global__ void scatter_kernel(const int* __restrict__ category, int B) {
    int i = blockIdx.x * blockDim.x + threadIdx.x;
    if (i < B) {
        int c = category[i];
        int p = atomicAdd(&g_counts[c], 1);
        g_idx[c * BMAX + p] = i;
    }
}

// ---------------------------------------------------------------------------
// tf32 helpers (3xTF32 compensated; numerics proven)
// ---------------------------------------------------------------------------
__device__ __forceinline__ float tf32_trunc(float v) {
    return __uint_as_float(__float_as_uint(v) & 0xFFFFE000u);
}

__device__ __forceinline__ void mma_tf32(float* c,
    float a0, float a1, float a2, float a3, float b0, float b1)
{
    asm volatile(
        "mma.sync.aligned.m16n8k8.row.col.f32.tf32.tf32.f32 "
        "{%0,%1,%2,%3}, {%4,%5,%6,%7}, {%8,%9}, {%0,%1,%2,%3};\n"
        : "+f"(c[0]), "+f"(c[1]), "+f"(c[2]), "+f"(c[3])
        : "r"(__float_as_uint(a0)), "r"(__float_as_uint(a1)),
          "r"(__float_as_uint(a2)), "r"(__float_as_uint(a3)),
          "r"(__float_as_uint(b0)), "r"(__float_as_uint(b1)));
}

// ---------------------------------------------------------------------------
// Generic DENSE 64x64 3xTF32 GEMM tile (proven; used by fusedA/fusedB).
// ---------------------------------------------------------------------------
__device__ __forceinline__ void mma_gemm64_tile(
    const float* __restrict__ A, int lda,
    const float* __restrict__ W, int ldw,
    const float* __restrict__ bias,
    float* __restrict__ C, int ldc,
    int M, int K, int mt, int colbase,
    float (*As)[16][68], float (*Bs)[16][68])
{
    const int t = threadIdx.x;
    const int lane = t & 31, wid = t >> 5;
    const int warp_m = wid & 3, warp_n = wid >> 2;
    const int gid = lane >> 2, tig = lane & 3;

    const int arow = t >> 2, akk = (t & 3) * 4;
    const int bk = t >> 4, bn = (t & 15) * 4;

    const int ga = mt * 64 + arow;
    const bool aload = (ga < M);
    const float* Ap = A + (size_t)(aload ? ga : 0) * lda;

    float acc[4][4];
    #pragma unroll
    for (int i = 0; i < 4; ++i)
        #pragma unroll
        for (int j = 0; j < 4; ++j) acc[i][j] = 0.f;

    const int NS = K / 16;
    float4 av = make_float4(0.f, 0.f, 0.f, 0.f);
    if (aload) av = *reinterpret_cast<const float4*>(Ap + akk);
    float4 bv = *reinterpret_cast<const float4*>(W + (size_t)bk * ldw + colbase + bn);
    As[0][akk + 0][arow] = av.x; As[0][akk + 1][arow] = av.y;
    As[0][akk + 2][arow] = av.z; As[0][akk + 3][arow] = av.w;
    *reinterpret_cast<float4*>(&Bs[0][bk][bn]) = bv;
    __syncthreads();

    const int am = warp_m * 16;
    const int bn0 = warp_n * 32;

    for (int s = 0; s < NS; ++s) {
        const int cur = s & 1;
        float4 av2 = make_float4(0.f, 0.f, 0.f, 0.f), bv2;
        if (s + 1 < NS) {
            const int k0 = (s + 1) * 16;
            if (aload) av2 = *reinterpret_cast<const float4*>(Ap + k0 + akk);
            bv2 = *reinterpret_cast<const float4*>(W + (size_t)(k0 + bk) * ldw + colbase + bn);
        }

        #pragma unroll
        for (int g = 0; g < 2; ++g) {
            const int ka = g * 8;
            float a0 = As[cur][ka + tig][am + gid];
            float a1 = As[cur][ka + tig][am + gid + 8];
            float a2 = As[cur][ka + tig + 4][am + gid];
            float a3 = As[cur][ka + tig + 4][am + gid + 8];
            float ah0 = tf32_trunc(a0), al0 = tf32_trunc(a0 - ah0);
            float ah1 = tf32_trunc(a1), al1 = tf32_trunc(a1 - ah1);
            float ah2 = tf32_trunc(a2), al2 = tf32_trunc(a2 - ah2);
            float ah3 = tf32_trunc(a3), al3 = tf32_trunc(a3 - ah3);
            #pragma unroll
            for (int nt = 0; nt < 4; ++nt) {
                const int bcol = bn0 + nt * 8 + gid;
                float b0 = Bs[cur][ka + tig][bcol];
                float b1 = Bs[cur][ka + tig + 4][bcol];
                float bh0 = tf32_trunc(b0), bl0 = tf32_trunc(b0 - bh0);
                float bh1 = tf32_trunc(b1), bl1 = tf32_trunc(b1 - bh1);
                mma_tf32(acc[nt], ah0, ah1, ah2, ah3, bh0, bh1);
                mma_tf32(acc[nt], ah0, ah1, ah2, ah3, bl0, bl1);
                mma_tf32(acc[nt], al0, al1, al2, al3, bh0, bh1);
            }
        }

        if (s + 1 < NS) {
            const int nb = cur ^ 1;
            As[nb][akk + 0][arow] = av2.x; As[nb][akk + 1][arow] = av2.y;
            As[nb][akk + 2][arow] = av2.z; As[nb][akk + 3][arow] = av2.w;
            *reinterpret_cast<float4*>(&Bs[nb][bk][bn]) = bv2;
        }
        __syncthreads();
    }

    const int r0 = mt * 64 + am + gid;
    const int r1 = r0 + 8;
    #pragma unroll
    for (int nt = 0; nt < 4; ++nt) {
        const int cn = bn0 + nt * 8 + 2 * tig;
        const float bb0 = bias[colbase + cn];
        const float bb1 = bias[colbase + cn + 1];
        if (r0 < M) {
            float2 o;
            o.x = fmaxf(acc[nt][0] + bb0, 0.f);
            o.y = fmaxf(acc[nt][1] + bb1, 0.f);
            *reinterpret_cast<float2*>(&C[(size_t)r0 * ldc + colbase + cn]) = o;
        }
        if (r1 < M) {
            float2 o;
            o.x = fmaxf(acc[nt][2] + bb0, 0.f);
            o.y = fmaxf(acc[nt][3] + bb1, 0.f);
            *reinterpret_cast<float2*>(&C[(size_t)r1 * ldc + colbase + cn]) = o;
        }
    }
}

// ---------------------------------------------------------------------------
// Expert + shared MLP, 3xTF32 with 32x64 tiles (2x real CTAs vs R11).
// 8 warps: warp_m = wid&1 (16 rows each), warp_n = wid>>1 (16 cols each).
// Fragment-level code identical to the proven 64x64 body; nt loop 4->2.
// ---------------------------------------------------------------------------
__global__ void __launch_bounds__(256) expert_mma_kernel(
    const float* __restrict__ pooled,
    const float* __restrict__ Wsh, const float* __restrict__ bsh,
    const float* __restrict__ Wsp, const float* __restrict__ bsp,
    int B)
{
    const int c = blockIdx.z;
    const bool dense = (c == NDOM);
    const int cnt = dense ? B : g_counts[c];
    const int mt = blockIdx.y;
    if (mt * 32 >= cnt) return;

    const float* W    = dense ? Wsh : (Wsp + (size_t)c * EDIM * HDIM);
    const float* bias = dense ? bsh : (bsp + c * HDIM);
    const int colbase = blockIdx.x * 64;
    const int outcol  = (dense ? 0 : HDIM) + colbase;

    __shared__ float As[2][16][36];   // [k][row 0..31]
    __shared__ float Bs[2][16][68];   // [k][n 0..63]

    const int t = threadIdx.x;
    const int lane = t & 31, wid = t >> 5;
    const int warp_m = wid & 1, warp_n = wid >> 1;   // 2 x 4
    const int gid = lane >> 2, tig = lane & 3;

    // loaders: A by threads t<128 (arow 0..31, akk 0..12), B by all 256
    const int arow = t >> 2, akk = (t & 3) * 4;
    const bool athr = (t < 128);
    const int bk = t >> 4, bn = (t & 15) * 4;

    int gi = -1;
    if (athr) {
        const int amrow = mt * 32 + arow;
        if (amrow < cnt) gi = dense ? amrow : g_idx[c * BMAX + amrow];
    }
    const float* Ap = pooled + (size_t)(gi >= 0 ? gi : 0) * EDIM;

    float acc[2][4];
    #pragma unroll
    for (int i = 0; i < 2; ++i)
        #pragma unroll
        for (int j = 0; j < 4; ++j) acc[i][j] = 0.f;

    const int NS = EDIM / 16;
    float4 av = make_float4(0.f, 0.f, 0.f, 0.f);
    if (gi >= 0) av = *reinterpret_cast<const float4*>(Ap + akk);
    float4 bv = *reinterpret_cast<const float4*>(W + (size_t)bk * HDIM + colbase + bn);
    if (athr) {
        As[0][akk + 0][arow] = av.x; As[0][akk + 1][arow] = av.y;
        As[0][akk + 2][arow] = av.z; As[0][akk + 3][arow] = av.w;
    }
    *reinterpret_cast<float4*>(&Bs[0][bk][bn]) = bv;
    __syncthreads();

    const int am = warp_m * 16;
    const int bn0 = warp_n * 16;

    for (int s = 0; s < NS; ++s) {
        const int cur = s & 1;
        float4 av2 = make_float4(0.f, 0.f, 0.f, 0.f), bv2;
        if (s + 1 < NS) {
            const int k0 = (s + 1) * 16;
            if (gi >= 0) av2 = *reinterpret_cast<const float4*>(Ap + k0 + akk);
            bv2 = *reinterpret_cast<const float4*>(W + (size_t)(k0 + bk) * HDIM + colbase + bn);
        }

        #pragma unroll
        for (int g = 0; g < 2; ++g) {
            const int ka = g * 8;
            float a0 = As[cur][ka + tig][am + gid];
            float a1 = As[cur][ka + tig][am + gid + 8];
            float a2 = As[cur][ka + tig + 4][am + gid];
            float a3 = As[cur][ka + tig + 4][am + gid + 8];
            float ah0 = tf32_trunc(a0), al0 = tf32_trunc(a0 - ah0);
            float ah1 = tf32_trunc(a1), al1 = tf32_trunc(a1 - ah1);
            float ah2 = tf32_trunc(a2), al2 = tf32_trunc(a2 - ah2);
            float ah3 = tf32_trunc(a3), al3 = tf32_trunc(a3 - ah3);
            #pragma unroll
            for (int nt = 0; nt < 2; ++nt) {
                const int bcol = bn0 + nt * 8 + gid;
                float b0 = Bs[cur][ka + tig][bcol];
                float b1 = Bs[cur][ka + tig + 4][bcol];
                float bh0 = tf32_trunc(b0), bl0 = tf32_trunc(b0 - bh0);
                float bh1 = tf32_trunc(b1), bl1 = tf32_trunc(b1 - bh1);
                mma_tf32(acc[nt], ah0, ah1, ah2, ah3, bh0, bh1);
                mma_tf32(acc[nt], ah0, ah1, ah2, ah3, bl0, bl1);
                mma_tf32(acc[nt], al0, al1, al2, al3, bh0, bh1);
            }
        }

        if (s + 1 < NS) {
            const int nb = cur ^ 1;
            if (athr) {
                As[nb][akk + 0][arow] = av2.x; As[nb][akk + 1][arow] = av2.y;
                As[nb][akk + 2][arow] = av2.z; As[nb][akk + 3][arow] = av2.w;
            }
            *reinterpret_cast<float4*>(&Bs[nb][bk][bn]) = bv2;
        }
        __syncthreads();
    }

    const int r0 = mt * 32 + am + gid;
    const int r1 = r0 + 8;
    int ridx0 = 0, ridx1 = 0;
    const bool v0 = (r0 < cnt), v1 = (r1 < cnt);
    if (v0) ridx0 = dense ? r0 : g_idx[c * BMAX + r0];
    if (v1) ridx1 = dense ? r1 : g_idx[c * BMAX + r1];

    #pragma unroll
    for (int nt = 0; nt < 2; ++nt) {
        const int cn = bn0 + nt * 8 + 2 * tig;
        const float bb0 = bias[colbase + cn];
        const float bb1 = bias[colbase + cn + 1];
        if (v0) {
            float2 o;
            o.x = fmaxf(acc[nt][0] + bb0, 0.f);
            o.y = fmaxf(acc[nt][1] + bb1, 0.f);
            *reinterpret_cast<float2*>(&g_feature[(size_t)ridx0 * EDIM + outcol + cn]) = o;
        }
        if (v1) {
            float2 o;
            o.x = fmaxf(acc[nt][2] + bb0, 0.f);
            o.y = fmaxf(acc[nt][3] + bb1, 0.f);
            *reinterpret_cast<float2*>(&g_feature[(size_t)ridx1 * EDIM + outcol + cn]) = o;
        }
    }
}

// ---------------------------------------------------------------------------
// fusedA: dec1 (32 mma tiles) + domain1 (192 mma tiles) + cls (warp/sample)
// ---------------------------------------------------------------------------
#define FA_DEC1 32
#define FA_DOM1 (FA_DEC1 + 192)
__global__ void __launch_bounds__(256) fusedA_kernel(
    const float* __restrict__ Wd1, const float* __restrict__ bd1,
    const float* __restrict__ Wdo1, const float* __restrict__ bdo1,
    const float* __restrict__ Wc, const float* __restrict__ bc,
    float* __restrict__ out, int B)
{
    __shared__ float As[2][16][68];
    __shared__ float Bs[2][16][68];
    const int bx = blockIdx.x;

    if (bx < FA_DEC1) {
        mma_gemm64_tile(g_feature, EDIM, Wd1, 64, bd1, g_h1, 64, B, EDIM,
                        bx, 0, As, Bs);
    } else if (bx < FA_DOM1) {
        const int idx = bx - FA_DEC1;
        mma_gemm64_tile(g_feature, EDIM, Wdo1, HDIM, bdo1, g_hdom, HDIM, B, HDIM,
                        idx / 6, (idx % 6) * 64, As, Bs);
    } else {
        const int sample = (bx - FA_DOM1) * 8 + (threadIdx.x >> 5);
        const int lane = threadIdx.x & 31;
        if (sample < B) {
            const float4* f = reinterpret_cast<const float4*>(g_feature + (size_t)sample * EDIM);
            const float4* wc = reinterpret_cast<const float4*>(Wc);
            float acc = 0.f;
            #pragma unroll
            for (int i = 0; i < 6; ++i) {
                float4 a = f[lane + 32 * i], ww = wc[lane + 32 * i];
                acc += a.x * ww.x + a.y * ww.y + a.z * ww.z + a.w * ww.w;
            }
            #pragma unroll
            for (int o = 16; o; o >>= 1) acc += __shfl_xor_sync(0xffffffffu, acc, o);
            if (lane == 0) out[sample] = 1.f / (1.f + __expf(-(acc + bc[0])));
        }
    }
}

// ---------------------------------------------------------------------------
// fusedB: dec2 (384 mma tiles) + domain2 (warp/sample)
// ---------------------------------------------------------------------------
#define FB_DEC2 384
__global__ void __launch_bounds__(256) fusedB_kernel(
    const float* __restrict__ Wd2, const float* __restrict__ bd2,
    const float* __restrict__ Wdo2, const float* __restrict__ bdo2,
    float* __restrict__ rec, float* __restrict__ dp, int B)
{
    __shared__ float As[2][16][68];
    __shared__ float Bs[2][16][68];
    const int bx = blockIdx.x;

    if (bx < FB_DEC2) {
        mma_gemm64_tile(g_h1, 64, Wd2, EDIM, bd2, rec, EDIM, B, 64,
                        bx / 12, (bx % 12) * 64, As, Bs);
    } else {
        const int sample = (bx - FB_DEC2) * 8 + (threadIdx.x >> 5);
        const int lane = threadIdx.x & 31;
        if (sample < B) {
            const float* h = g_hdom + (size_t)sample * HDIM;
            float a[NDOM];
            #pragma unroll
            for (int j = 0; j < NDOM; ++j) a[j] = 0.f;
            #pragma unroll
            for (int i = 0; i < 3; ++i) {
                const int k = (lane + 32 * i) * 4;
                float4 hv = *reinterpret_cast<const float4*>(h + k);
                float hh[4] = {hv.x, hv.y, hv.z, hv.w};
                #pragma unroll
                for (int q = 0; q < 4; ++q) {
                    const float* wrow = Wdo2 + (k + q) * NDOM;
                    #pragma unroll
                    for (int j = 0; j < NDOM; ++j) a[j] += hh[q] * wrow[j];
                }
            }
            #pragma unroll
            for (int j = 0; j < NDOM; ++j) {
                #pragma unroll
                for (int o = 16; o; o >>= 1) a[j] += __shfl_xor_sync(0xffffffffu, a[j], o);
            }
            if (lane == 0) {
                #pragma unroll
                for (int j = 0; j < NDOM; ++j)
                    dp[(size_t)sample * NDOM + j] = a[j] + bdo2[j];
            }
        }
    }
}

// ---------------------------------------------------------------------------
extern "C" void kernel_launch(void* const* d_in, const int* in_sizes, int n_in,
                              void* d_out, int out_size)
{
    const float* bert     = (const float*)d_in[0];
    const int*   masks    = (const int*)d_in[1];
    const int*   category = (const int*)d_in[2];
    const float* att_w = (const float*)d_in[4];
    const float* att_b = (const float*)d_in[5];
    const float* Wsh = (const float*)d_in[6];  const float* bsh = (const float*)d_in[7];
    const float* Wsp = (const float*)d_in[8];  const float* bsp = (const float*)d_in[9];
    const float* Wd1 = (const float*)d_in[10]; const float* bd1 = (const float*)d_in[11];
    const float* Wd2 = (const float*)d_in[12]; const float* bd2 = (const float*)d_in[13];
    const float* Wc  = (const float*)d_in[14]; const float* bc  = (const float*)d_in[15];
    const float* Wdo1 = (const float*)d_in[16]; const float* bdo1 = (const float*)d_in[17];
    const float* Wdo2 = (const float*)d_in[18]; const float* bdo2 = (const float*)d_in[19];

    const int B = in_sizes[2];

    float* out    = (float*)d_out;
    float* rec    = out + B;
    float* pooled = rec + (size_t)B * EDIM;
    float* dp     = pooled + (size_t)B * EDIM;

    // routing lists (off the data critical path)
    zero_counts_kernel<<<1, 16>>>();
    scatter_kernel<<<(B + 255) / 256, 256>>>(category, B);

    pool_kernel<<<B, 192>>>(bert, masks, att_w, att_b, pooled);

    // shared MLP (slab 9) + 9 specific experts: 3xTF32, 32-row tiles
    expert_mma_kernel<<<dim3(HDIM / 64, (B + 31) / 32, NDOM + 1), 256>>>(
        pooled, Wsh, bsh, Wsp, bsp, B);

    // fusedA: dec1 + domain1 + cls (all read g_feature)
    fusedA_kernel<<<FA_DOM1 + (B + 7) / 8, 256>>>(
        Wd1, bd1, Wdo1, bdo1, Wc, bc, out, B);

    // fusedB: dec2 + domain2
    fusedB_kernel<<<FB_DEC2 + (B + 7) / 8, 256>>>(
        Wd2, bd2, Wdo2, bdo2, rec, dp, B);
}